// round 10
// baseline (speedup 1.0000x reference)
#include <cuda_runtime.h>

// Reference collapses to a constant: entmax_bisect over a last dim of size 1
// returns exactly 1.0 for every row, independent of all inputs
// (d=1 -> tau_hi == tau_lo -> p_m = clip(1)^(1/(a-1)) = 1 exactly; 1/sum(1) = 1).
// Output = ones([131072, 1]) bit-exact in fp32.
//
// Floor established: all pipes <2%, kernel dur = fixed launch/ramp (v8 variant
// reproducibly 3.55-3.62us), e2e 5.0-5.8us uncorrelated with kernel dur.
// R9 change: halve CTA count 64 -> 32 (256-thread blocks kept; R7 showed the
// 1024-thread BLOCK SHAPE was bad, CTA count untested). Each thread: two
// unrolled 256-bit stores, 64 B apart per thread, fully coalesced.

__global__ void __launch_bounds__(256) fill_ones_v8x2(float* __restrict__ out) {
    // each thread writes 16 floats (2 x 256-bit stores)
    unsigned idx = (blockIdx.x * 256u + threadIdx.x) * 16u;
    float* p = out + idx;
    asm volatile(
        "st.global.v8.f32 [%0],     {%1, %1, %1, %1, %1, %1, %1, %1};\n\t"
        "st.global.v8.f32 [%0+32],  {%1, %1, %1, %1, %1, %1, %1, %1};"
        :: "l"(p), "f"(1.0f) : "memory");
}

__global__ void __launch_bounds__(256) fill_ones_guarded(float* __restrict__ out, int n) {
    int i4 = blockIdx.x * blockDim.x + threadIdx.x;
    int base = i4 << 2;
    if (base + 3 < n) {
        reinterpret_cast<float4*>(out)[i4] = make_float4(1.0f, 1.0f, 1.0f, 1.0f);
    } else {
        for (int j = base; j < n; ++j) out[j] = 1.0f;
    }
}

extern "C" void kernel_launch(void* const* d_in, const int* in_sizes, int n_in,
                              void* d_out, int out_size) {
    (void)d_in; (void)in_sizes; (void)n_in;
    int n = out_size;                        // 131072 expected
    // exact fit: n divisible by 16*256 = 4096 -> branchless v8x2 kernel
    if ((n & 4095) == 0) {
        int blocks = n / 4096;               // 32 for n=131072
        fill_ones_v8x2<<<blocks, 256>>>((float*)d_out);
    } else {
        int n4 = (n + 3) >> 2;
        int blocks = (n4 + 255) / 256;
        fill_ones_guarded<<<blocks, 256>>>((float*)d_out, n);
    }
}

// round 11
// speedup vs baseline: 1.2000x; 1.2000x over previous
#include <cuda_runtime.h>

// Reference collapses to a constant: entmax_bisect over a last dim of size 1
// returns exactly 1.0 for every row, independent of all inputs
// (d=1 -> tau_hi == tau_lo -> p_m = clip(1)^(1/(a-1)) = 1 exactly; 1/sum(1) = 1).
// Output = ones([131072, 1]) bit-exact in fp32.
//
// Geometry sweep complete: 64 CTAs x 256 thr x 1 v8-store is measured-best
// kernel config (3.55-3.62us); 128x256/f4=3.74-3.87, 32x1024=4.26,
// 32x256/v8x2=3.81. All pipes <2% -> fixed launch/ramp floor. e2e (5.0-5.95us)
// is harness noise, uncorrelated with kernel dur. Reverted to the best variant.

__global__ void __launch_bounds__(256) fill_ones_v8(float* __restrict__ out) {
    // each thread writes 8 floats (32 B) with one 256-bit store
    unsigned idx = (blockIdx.x * 256u + threadIdx.x) * 8u;
    float* p = out + idx;
    asm volatile(
        "st.global.v8.f32 [%0], {%1, %1, %1, %1, %1, %1, %1, %1};"
        :: "l"(p), "f"(1.0f) : "memory");
}

__global__ void __launch_bounds__(256) fill_ones_guarded(float* __restrict__ out, int n) {
    int i4 = blockIdx.x * blockDim.x + threadIdx.x;
    int base = i4 << 2;
    if (base + 3 < n) {
        reinterpret_cast<float4*>(out)[i4] = make_float4(1.0f, 1.0f, 1.0f, 1.0f);
    } else {
        for (int j = base; j < n; ++j) out[j] = 1.0f;
    }
}

extern "C" void kernel_launch(void* const* d_in, const int* in_sizes, int n_in,
                              void* d_out, int out_size) {
    (void)d_in; (void)in_sizes; (void)n_in;
    int n = out_size;                       // 131072 expected
    // exact fit: n divisible by 8*256 = 2048 -> branchless v8 kernel
    if ((n & 2047) == 0) {
        int blocks = n / 2048;              // 64 for n=131072
        fill_ones_v8<<<blocks, 256>>>((float*)d_out);
    } else {
        int n4 = (n + 3) >> 2;
        int blocks = (n4 + 255) / 256;
        fill_ones_guarded<<<blocks, 256>>>((float*)d_out, n);
    }
}